// round 14
// baseline (speedup 1.0000x reference)
#include <cuda_runtime.h>
#include <cstdint>

#define NIN      2049   // inputs per frame
#define NOUT     1024   // outputs per frame
#define ROWS     6      // frames per CTA -> grid = 267, 2 CTAs/SM, single wave
#define SXS      2052   // padded sx row stride: even + 16B-multiple
#define THREADS  1024

#define WCAP     16384  // >= n_tri * pstride (228*44 = 10032)
#define JCAP     1024

__device__ float4 g_wsh4[WCAP / 4];   // shift-compensated padded weights [j][pstride]
__device__ int2   g_meta[JCAP];       // {i0e (even window base), klen2 (float2 trips)}

// ---- Prep: per-j alignment normalization (runs once, off critical path) --
__global__ void prep_kernel(const float* __restrict__ triw,
                            const int*   __restrict__ tridx,
                            int n_tri, int max_w, int pstride)
{
    const int j = blockIdx.x * blockDim.x + threadIdx.x;
    if (j >= n_tri) return;
    float* g_wsh = (float*)g_wsh4;
    const float* wrow = triw + (size_t)j * max_w;

    int len = 0;                                   // first -inf = end of window
    while (len < max_w && __float_as_int(wrow[len]) != (int)0xff800000) len++;

    const int i0    = tridx[(size_t)j * max_w];    // first entry always valid
    const int shift = i0 & 1;
    const int i0e   = i0 - shift;
    const int klen2 = (shift + len + 1) >> 1;      // float2 trip count
    g_meta[j] = make_int2(i0e, klen2);

    for (int k = 0; k < pstride; k++) {
        const float v = (k >= shift && k < shift + len)
                      ? wrow[k - shift] : __int_as_float(0xff800000);
        g_wsh[j * pstride + k] = v;                // wsh[k] pairs with x[i0e + k]
    }
}

// ---- Main ---------------------------------------------------------------
__global__ void __launch_bounds__(THREADS, 2)
logscale_kernel(const float* __restrict__ x,
                const float* __restrict__ frac,
                const float* __restrict__ cubt,
                const int*   __restrict__ pair,
                const int*   __restrict__ cubi,
                float* __restrict__ out,
                int n_rows, int n_lin, int n_cub, int n_tri, int pstride)
{
    // Shared: sx[ROWS*SXS] | swt[n_tri*pstride]  (swt base 16B-aligned)
    extern __shared__ float smem_pool[];
    float* sx  = smem_pool;
    float* swt = smem_pool + ROWS * SXS;

    const int row0  = blockIdx.x * ROWS;
    const int nr    = min(ROWS, n_rows - row0);
    const int t     = threadIdx.x;
    const int n_sum = n_lin + n_cub;
    const float NEG_INF = __int_as_float(0xff800000);

    // Stage x rows into padded-stride smem (coalesced scalar, 2 passes/row).
    #pragma unroll
    for (int r = 0; r < ROWS; r++) {
        if (r < nr) {
            const float* s = x + (size_t)(row0 + r) * NIN;
            float* d = sx + r * SXS;
            d[t]            = __ldg(s + t);
            d[t + THREADS]  = __ldg(s + t + THREADS);
            if (t == 0) d[2048] = __ldg(s + 2048);
        }
    }
    // Stage prepped weights (float4, fully coalesced).
    {
        float4* d4 = (float4*)swt;
        const int nv4 = (n_tri * pstride) >> 2;
        for (int i = t; i < nv4; i += THREADS) d4[i] = g_wsh4[i];
    }
    __syncthreads();

    // ---- Triangular: task = (j, 3-row half); j DESCENDING in thread id ---
    // All accesses float2-aligned: i0e even, SXS even. -inf padding (head
    // shift + tail) is a no-op under fmax. Exact trip count, no branches.
    if (t < 2 * n_tri) {
        const int  j    = n_tri - 1 - (t >> 1);
        const int  q3   = (t & 1) * 3;             // rows q3..q3+2
        const int2 meta = __ldg(&g_meta[j]);
        const float2* __restrict__ wp = (const float2*)(swt + j * pstride);
        const float2* __restrict__ p0 = (const float2*)(sx + q3 * SXS + meta.x);
        const float2* __restrict__ p1 = (const float2*)(sx + (q3 + 1) * SXS + meta.x);
        const float2* __restrict__ p2 = (const float2*)(sx + (q3 + 2) * SXS + meta.x);

        float m0 = NEG_INF, m1 = NEG_INF, m2 = NEG_INF;
        #pragma unroll 4
        for (int k = 0; k < meta.y; k++) {
            const float2 wg = wp[k];
            const float2 a = p0[k], b = p1[k], c = p2[k];
            m0 = fmaxf(m0, fmaxf(a.x + wg.x, a.y + wg.y));
            m1 = fmaxf(m1, fmaxf(b.x + wg.x, b.y + wg.y));
            m2 = fmaxf(m2, fmaxf(c.x + wg.x, c.y + wg.y));
        }
        const int o = n_sum + j;
        if (q3 + 0 < nr) out[(size_t)(row0 + q3 + 0) * NOUT + o] = m0;
        if (q3 + 1 < nr) out[(size_t)(row0 + q3 + 1) * NOUT + o] = m1;
        if (q3 + 2 < nr) out[(size_t)(row0 + q3 + 2) * NOUT + o] = m2;
    }

    // ---- Linear + cubic on the high threads ------------------------------
    {
        const int o = t - (THREADS - n_sum);
        if (o >= 0) {
            if (o < n_lin) {
                const int   i0 = __ldg(pair + o);
                const float f  = __ldg(frac + o);
                #pragma unroll
                for (int r = 0; r < ROWS; r++) {
                    const float x0 = sx[r * SXS + i0];
                    const float x1 = sx[r * SXS + i0 + 1];
                    if (r < nr)
                        out[(size_t)(row0 + r) * NOUT + o] = x0 + f * (x1 - x0);
                }
            } else {
                const int   j  = o - n_lin;
                const int   i0 = __ldg(cubi + j);
                const float tc = __ldg(cubt + j);
                #pragma unroll
                for (int r = 0; r < ROWS; r++) {
                    const float* row = sx + r * SXS;
                    const float xm1 = row[i0 - 1];
                    const float x0  = row[i0];
                    const float x1  = row[i0 + 1];
                    const float x2  = row[i0 + 2];
                    const float v = x0 + 0.5f * tc * (x1 - xm1
                                  + tc * (2.0f * xm1 - 5.0f * x0 + 4.0f * x1 - x2
                                  + tc * (3.0f * (x0 - x1) + x2 - xm1)));
                    if (r < nr)
                        out[(size_t)(row0 + r) * NOUT + o] = v;
                }
            }
        }
    }
}

extern "C" void kernel_launch(void* const* d_in, const int* in_sizes, int n_in,
                              void* d_out, int out_size)
{
    const float* x     = (const float*)d_in[0];
    const float* frac  = (const float*)d_in[1];
    const float* cubt  = (const float*)d_in[2];
    const float* triw  = (const float*)d_in[3];
    const int*   pair  = (const int*)d_in[4];
    const int*   cubi  = (const int*)d_in[5];
    const int*   tridx = (const int*)d_in[6];
    float* out = (float*)d_out;

    const int n_lin  = in_sizes[1];
    const int n_cub  = in_sizes[2];
    const int n_tri  = NOUT - n_lin - n_cub;
    const int max_w  = (n_tri > 0) ? in_sizes[3] / n_tri : 0;
    const int n_rows = in_sizes[0] / NIN;
    const int pstride = ((max_w + 1 + 3) >> 2) << 2;   // 44 for max_w=40

    if (n_tri > 0)
        prep_kernel<<<(n_tri + 255) / 256, 256>>>(triw, tridx, n_tri, max_w, pstride);

    // smem: padded x tile + prepped weights  (~87.3 KB -> 2 CTAs/SM)
    const int smem = (ROWS * SXS + n_tri * pstride) * (int)sizeof(float);
    cudaFuncSetAttribute(logscale_kernel,
                         cudaFuncAttributeMaxDynamicSharedMemorySize, smem);

    const int grid = (n_rows + ROWS - 1) / ROWS;       // 267 CTAs
    logscale_kernel<<<grid, THREADS, smem>>>(x, frac, cubt, pair, cubi, out,
                                             n_rows, n_lin, n_cub, n_tri, pstride);
}

// round 16
// speedup vs baseline: 1.4847x; 1.4847x over previous
#include <cuda_runtime.h>
#include <cstdint>

#define NIN      2049   // inputs per frame
#define NOUT     1024   // outputs per frame
#define ROWS     6      // frames per CTA -> grid = 267, 2 CTAs/SM, single wave
#define SXS      2052   // padded sx row stride: even + 16B-multiple
#define THREADS  1024

#define W2CAP    8192   // float2 entries >= n_tri * pstride2 (228*22 = 5016)
#define JCAP     1024

__device__ float2 g_w2T[W2CAP];  // pair-major shifted weights: [k * n_tri + j]
__device__ int2   g_meta[JCAP];  // {i0e (even window base), klen2 (pair trips)}

// ---- Prep v2: one WARP per j; ballot-scan, fully parallel ---------------
__global__ void prep_kernel(const float* __restrict__ triw,
                            const int*   __restrict__ tridx,
                            int n_tri, int max_w, int pstride2)
{
    const int warp = (blockIdx.x * blockDim.x + threadIdx.x) >> 5;
    const int lane = threadIdx.x & 31;
    if (warp >= n_tri) return;
    const float NEG_INF = __int_as_float(0xff800000);
    const float* wrow = triw + (size_t)warp * max_w;

    // Window length = index of first -inf (parallel ballot, no serial chain).
    float v0 = (lane < max_w) ? __ldg(wrow + lane) : 0.0f;
    unsigned b1 = __ballot_sync(0xffffffffu,
                     lane < max_w && __float_as_int(v0) == (int)0xff800000);
    int len;
    if (b1) {
        len = __ffs(b1) - 1;
    } else {
        float v1 = (lane + 32 < max_w) ? __ldg(wrow + lane + 32) : 0.0f;
        unsigned b2 = __ballot_sync(0xffffffffu,
                        lane + 32 < max_w && __float_as_int(v1) == (int)0xff800000);
        len = b2 ? (32 + __ffs(b2) - 1) : max_w;
    }

    const int i0    = __ldg(tridx + (size_t)warp * max_w);  // first entry valid
    const int shift = i0 & 1;
    const int klen2 = (shift + len + 1) >> 1;
    if (lane == 0) g_meta[warp] = make_int2(i0 - shift, klen2);

    // Lane k emits pair k of the shift-compensated window (head/tail = -inf).
    if (lane < pstride2) {
        const int w1 = 2 * lane - shift;
        const int w2 = w1 + 1;
        const float wx = (w1 >= 0 && w1 < len) ? __ldg(wrow + w1) : NEG_INF;
        const float wy = (w2 >= 0 && w2 < len) ? __ldg(wrow + w2) : NEG_INF;
        g_w2T[lane * n_tri + warp] = make_float2(wx, wy);
    }
}

// ---- Main ---------------------------------------------------------------
__global__ void __launch_bounds__(THREADS, 2)
logscale_kernel(const float* __restrict__ x,
                const float* __restrict__ frac,
                const float* __restrict__ cubt,
                const int*   __restrict__ pair,
                const int*   __restrict__ cubi,
                float* __restrict__ out,
                int n_rows, int n_lin, int n_cub, int n_tri)
{
    extern __shared__ float sx[];      // ROWS*SXS floats = 49.2 KB (dynamic,
                                       // opt-in; static smem caps at 48 KB)

    const int row0  = blockIdx.x * ROWS;
    const int nr    = min(ROWS, n_rows - row0);
    const int t     = threadIdx.x;
    const int n_sum = n_lin + n_cub;
    const float NEG_INF = __int_as_float(0xff800000);

    // Stage x rows into padded-stride smem (coalesced scalar, 2 passes/row).
    #pragma unroll
    for (int r = 0; r < ROWS; r++) {
        if (r < nr) {
            const float* s = x + (size_t)(row0 + r) * NIN;
            float* d = sx + r * SXS;
            d[t]           = __ldg(s + t);
            d[t + THREADS] = __ldg(s + t + THREADS);
            if (t == 0) d[2048] = __ldg(s + 2048);
        }
    }
    __syncthreads();

    // ---- Triangular: task = (j, 3-row half); j DESCENDING in thread id ---
    // x pairs from smem (float2-aligned: i0e even, SXS even); weights from
    // the global pair-major table (16 consecutive j per warp -> 128B/wavefront,
    // L1-resident after first touch). Exact trip count from meta.
    if (t < 2 * n_tri) {
        const int  j    = n_tri - 1 - (t >> 1);
        const int  q3   = (t & 1) * 3;             // rows q3..q3+2
        const int2 meta = __ldg(&g_meta[j]);
        const float2* __restrict__ p0 = (const float2*)(sx + q3 * SXS + meta.x);
        const float2* __restrict__ p1 = (const float2*)(sx + (q3 + 1) * SXS + meta.x);
        const float2* __restrict__ p2 = (const float2*)(sx + (q3 + 2) * SXS + meta.x);
        const float2* __restrict__ wp = g_w2T + j;

        float m0 = NEG_INF, m1 = NEG_INF, m2 = NEG_INF;
        #pragma unroll 4
        for (int k = 0; k < meta.y; k++) {
            const float2 wg = __ldg(wp + k * n_tri);
            const float2 a = p0[k], b = p1[k], c = p2[k];
            m0 = fmaxf(m0, fmaxf(a.x + wg.x, a.y + wg.y));
            m1 = fmaxf(m1, fmaxf(b.x + wg.x, b.y + wg.y));
            m2 = fmaxf(m2, fmaxf(c.x + wg.x, c.y + wg.y));
        }
        const int o = n_sum + j;
        if (q3 + 0 < nr) out[(size_t)(row0 + q3 + 0) * NOUT + o] = m0;
        if (q3 + 1 < nr) out[(size_t)(row0 + q3 + 1) * NOUT + o] = m1;
        if (q3 + 2 < nr) out[(size_t)(row0 + q3 + 2) * NOUT + o] = m2;
    }

    // ---- Linear + cubic on the high threads ------------------------------
    {
        const int o = t - (THREADS - n_sum);
        if (o >= 0) {
            if (o < n_lin) {
                const int   i0 = __ldg(pair + o);
                const float f  = __ldg(frac + o);
                #pragma unroll
                for (int r = 0; r < ROWS; r++) {
                    const float x0 = sx[r * SXS + i0];
                    const float x1 = sx[r * SXS + i0 + 1];
                    if (r < nr)
                        out[(size_t)(row0 + r) * NOUT + o] = x0 + f * (x1 - x0);
                }
            } else {
                const int   j  = o - n_lin;
                const int   i0 = __ldg(cubi + j);
                const float tc = __ldg(cubt + j);
                #pragma unroll
                for (int r = 0; r < ROWS; r++) {
                    const float* row = sx + r * SXS;
                    const float xm1 = row[i0 - 1];
                    const float x0  = row[i0];
                    const float x1  = row[i0 + 1];
                    const float x2  = row[i0 + 2];
                    const float v = x0 + 0.5f * tc * (x1 - xm1
                                  + tc * (2.0f * xm1 - 5.0f * x0 + 4.0f * x1 - x2
                                  + tc * (3.0f * (x0 - x1) + x2 - xm1)));
                    if (r < nr)
                        out[(size_t)(row0 + r) * NOUT + o] = v;
                }
            }
        }
    }
}

extern "C" void kernel_launch(void* const* d_in, const int* in_sizes, int n_in,
                              void* d_out, int out_size)
{
    const float* x     = (const float*)d_in[0];
    const float* frac  = (const float*)d_in[1];
    const float* cubt  = (const float*)d_in[2];
    const float* triw  = (const float*)d_in[3];
    const int*   pair  = (const int*)d_in[4];
    const int*   cubi  = (const int*)d_in[5];
    const int*   tridx = (const int*)d_in[6];
    float* out = (float*)d_out;

    const int n_lin  = in_sizes[1];
    const int n_cub  = in_sizes[2];
    const int n_tri  = NOUT - n_lin - n_cub;
    const int max_w  = (n_tri > 0) ? in_sizes[3] / n_tri : 0;
    const int n_rows = in_sizes[0] / NIN;
    const int pstride2 = (max_w >> 1) + 2;             // 22 for max_w=40

    if (n_tri > 0) {
        const int warps_per_blk = 8;                   // 256 threads
        const int blocks = (n_tri + warps_per_blk - 1) / warps_per_blk;
        prep_kernel<<<blocks, warps_per_blk * 32>>>(triw, tridx,
                                                    n_tri, max_w, pstride2);
    }

    const int smem = ROWS * SXS * (int)sizeof(float);  // 49248 B dynamic
    cudaFuncSetAttribute(logscale_kernel,
                         cudaFuncAttributeMaxDynamicSharedMemorySize, smem);

    const int grid = (n_rows + ROWS - 1) / ROWS;       // 267 CTAs
    logscale_kernel<<<grid, THREADS, smem>>>(x, frac, cubt, pair, cubi, out,
                                             n_rows, n_lin, n_cub, n_tri);
}

// round 17
// speedup vs baseline: 1.6347x; 1.1010x over previous
#include <cuda_runtime.h>
#include <cstdint>

#define NIN      2049   // inputs per frame
#define NOUT     1024   // outputs per frame
#define ROWS     6      // frames per CTA -> grid = 267, 2 CTAs/SM, single wave
#define SXS      2052   // padded sx row stride: even + 16B-multiple
#define THREADS  1024

#define W2CAP    8192   // float2 entries >= n_tri * pstride2 (228*22 = 5016)
#define JCAP     1024

__device__ float2 g_w2T[W2CAP];  // pair-major shifted weights: [k * n_tri + j]
__device__ int2   g_meta[JCAP];  // {i0e (even window base), klen2 (pair trips)}

__device__ __forceinline__ void cp16(uint32_t dst, const void* src) {
    asm volatile("cp.async.cg.shared.global [%0], [%1], 16;"
                 :: "r"(dst), "l"(src) : "memory");
}

// ---- Prep: one WARP per j; ballot-scan, fully parallel (measured fast) ---
__global__ void prep_kernel(const float* __restrict__ triw,
                            const int*   __restrict__ tridx,
                            int n_tri, int max_w, int pstride2)
{
    const int warp = (blockIdx.x * blockDim.x + threadIdx.x) >> 5;
    const int lane = threadIdx.x & 31;
    if (warp >= n_tri) return;
    const float NEG_INF = __int_as_float(0xff800000);
    const float* wrow = triw + (size_t)warp * max_w;

    float v0 = (lane < max_w) ? __ldg(wrow + lane) : 0.0f;
    unsigned b1 = __ballot_sync(0xffffffffu,
                     lane < max_w && __float_as_int(v0) == (int)0xff800000);
    int len;
    if (b1) {
        len = __ffs(b1) - 1;
    } else {
        float v1 = (lane + 32 < max_w) ? __ldg(wrow + lane + 32) : 0.0f;
        unsigned b2 = __ballot_sync(0xffffffffu,
                        lane + 32 < max_w && __float_as_int(v1) == (int)0xff800000);
        len = b2 ? (32 + __ffs(b2) - 1) : max_w;
    }

    const int i0    = __ldg(tridx + (size_t)warp * max_w);  // first entry valid
    const int shift = i0 & 1;
    const int klen2 = (shift + len + 1) >> 1;
    if (lane == 0) g_meta[warp] = make_int2(i0 - shift, klen2);

    if (lane < pstride2) {
        const int w1 = 2 * lane - shift;
        const int w2 = w1 + 1;
        const float wx = (w1 >= 0 && w1 < len) ? __ldg(wrow + w1) : NEG_INF;
        const float wy = (w2 >= 0 && w2 < len) ? __ldg(wrow + w2) : NEG_INF;
        g_w2T[lane * n_tri + warp] = make_float2(wx, wy);
    }
}

// ---- Main ---------------------------------------------------------------
__global__ void __launch_bounds__(THREADS, 2)
logscale_kernel(const float* __restrict__ x,
                const float* __restrict__ frac,
                const float* __restrict__ cubt,
                const int*   __restrict__ pair,
                const int*   __restrict__ cubi,
                float* __restrict__ out,
                int n_rows, int n_lin, int n_cub, int n_tri, int pstride2)
{
    // Shared: sx[ROWS*SXS] | swt2[n_tri*pstride2 float2]  (~89.4 KB)
    extern __shared__ float smem_pool[];
    float*  sx   = smem_pool;
    float2* swt2 = (float2*)(smem_pool + ROWS * SXS);   // 16B-aligned offset

    const int row0  = blockIdx.x * ROWS;
    const int nr    = min(ROWS, n_rows - row0);
    const int t     = threadIdx.x;
    const int n_sum = n_lin + n_cub;
    const float NEG_INF = __int_as_float(0xff800000);

    // 1) Weight table via cp.async (issue-only, DMA overlaps x staging).
    {
        const uint32_t dstb = (uint32_t)__cvta_generic_to_shared(swt2);
        const int nv4 = (n_tri * pstride2) >> 1;        // float4 chunks (2508)
        #pragma unroll
        for (int u = 0; u < 3; u++) {
            const int i = t + u * THREADS;
            if (i < nv4) cp16(dstb + i * 16, (const float4*)g_w2T + i);
        }
        asm volatile("cp.async.commit_group;" ::: "memory");
    }

    // 2) x rows: front-batched register staging (two MLP-6 batches).
    {
        float a[6], b[6];
        #pragma unroll
        for (int r = 0; r < ROWS; r++)
            a[r] = (r < nr) ? __ldg(x + (size_t)(row0 + r) * NIN + t) : 0.0f;
        #pragma unroll
        for (int r = 0; r < ROWS; r++)
            b[r] = (r < nr) ? __ldg(x + (size_t)(row0 + r) * NIN + t + THREADS) : 0.0f;
        #pragma unroll
        for (int r = 0; r < ROWS; r++) sx[r * SXS + t] = a[r];
        #pragma unroll
        for (int r = 0; r < ROWS; r++) sx[r * SXS + t + THREADS] = b[r];
        if (t < ROWS && t < nr)
            sx[t * SXS + 2048] = __ldg(x + (size_t)(row0 + t) * NIN + 2048);
    }

    asm volatile("cp.async.wait_group 0;" ::: "memory");
    __syncthreads();

    // 3) Triangular: task = (j, 3-row half); j DESCENDING in thread id.
    //    All float2-aligned (i0e even, SXS even); -inf padding is a no-op
    //    under fmax; exact trip count from meta. Weights from smem: for a
    //    fixed k a warp touches 16 consecutive j -> 128B, conflict-free.
    if (t < 2 * n_tri) {
        const int  j    = n_tri - 1 - (t >> 1);
        const int  q3   = (t & 1) * 3;                  // rows q3..q3+2
        const int2 meta = __ldg(&g_meta[j]);
        const float2* __restrict__ p0 = (const float2*)(sx + q3 * SXS + meta.x);
        const float2* __restrict__ p1 = (const float2*)(sx + (q3 + 1) * SXS + meta.x);
        const float2* __restrict__ p2 = (const float2*)(sx + (q3 + 2) * SXS + meta.x);
        const float2* __restrict__ wp = swt2 + j;

        float m0 = NEG_INF, m1 = NEG_INF, m2 = NEG_INF;
        #pragma unroll 4
        for (int k = 0; k < meta.y; k++) {
            const float2 wg = wp[k * n_tri];
            const float2 a = p0[k], b = p1[k], c = p2[k];
            m0 = fmaxf(m0, fmaxf(a.x + wg.x, a.y + wg.y));
            m1 = fmaxf(m1, fmaxf(b.x + wg.x, b.y + wg.y));
            m2 = fmaxf(m2, fmaxf(c.x + wg.x, c.y + wg.y));
        }
        const int o = n_sum + j;
        if (q3 + 0 < nr) out[(size_t)(row0 + q3 + 0) * NOUT + o] = m0;
        if (q3 + 1 < nr) out[(size_t)(row0 + q3 + 1) * NOUT + o] = m1;
        if (q3 + 2 < nr) out[(size_t)(row0 + q3 + 2) * NOUT + o] = m2;
    }

    // 4) Linear + cubic on the high threads.
    {
        const int o = t - (THREADS - n_sum);
        if (o >= 0) {
            if (o < n_lin) {
                const int   i0 = __ldg(pair + o);
                const float f  = __ldg(frac + o);
                #pragma unroll
                for (int r = 0; r < ROWS; r++) {
                    const float x0 = sx[r * SXS + i0];
                    const float x1 = sx[r * SXS + i0 + 1];
                    if (r < nr)
                        out[(size_t)(row0 + r) * NOUT + o] = x0 + f * (x1 - x0);
                }
            } else {
                const int   j  = o - n_lin;
                const int   i0 = __ldg(cubi + j);
                const float tc = __ldg(cubt + j);
                #pragma unroll
                for (int r = 0; r < ROWS; r++) {
                    const float* row = sx + r * SXS;
                    const float xm1 = row[i0 - 1];
                    const float x0  = row[i0];
                    const float x1  = row[i0 + 1];
                    const float x2  = row[i0 + 2];
                    const float v = x0 + 0.5f * tc * (x1 - xm1
                                  + tc * (2.0f * xm1 - 5.0f * x0 + 4.0f * x1 - x2
                                  + tc * (3.0f * (x0 - x1) + x2 - xm1)));
                    if (r < nr)
                        out[(size_t)(row0 + r) * NOUT + o] = v;
                }
            }
        }
    }
}

extern "C" void kernel_launch(void* const* d_in, const int* in_sizes, int n_in,
                              void* d_out, int out_size)
{
    const float* x     = (const float*)d_in[0];
    const float* frac  = (const float*)d_in[1];
    const float* cubt  = (const float*)d_in[2];
    const float* triw  = (const float*)d_in[3];
    const int*   pair  = (const int*)d_in[4];
    const int*   cubi  = (const int*)d_in[5];
    const int*   tridx = (const int*)d_in[6];
    float* out = (float*)d_out;

    const int n_lin  = in_sizes[1];
    const int n_cub  = in_sizes[2];
    const int n_tri  = NOUT - n_lin - n_cub;
    const int max_w  = (n_tri > 0) ? in_sizes[3] / n_tri : 0;
    const int n_rows = in_sizes[0] / NIN;
    const int pstride2 = (max_w >> 1) + 2;             // 22 for max_w=40

    if (n_tri > 0) {
        const int warps_per_blk = 8;
        const int blocks = (n_tri + warps_per_blk - 1) / warps_per_blk;
        prep_kernel<<<blocks, warps_per_blk * 32>>>(triw, tridx,
                                                    n_tri, max_w, pstride2);
    }

    // smem: padded x tile + pair-major weight table
    const int smem = (ROWS * SXS + n_tri * pstride2 * 2) * (int)sizeof(float);
    cudaFuncSetAttribute(logscale_kernel,
                         cudaFuncAttributeMaxDynamicSharedMemorySize, smem);

    const int grid = (n_rows + ROWS - 1) / ROWS;       // 267 CTAs
    logscale_kernel<<<grid, THREADS, smem>>>(x, frac, cubt, pair, cubi, out,
                                             n_rows, n_lin, n_cub, n_tri, pstride2);
}